// round 2
// baseline (speedup 1.0000x reference)
#include <cuda_runtime.h>
#include <cuda_bf16.h>

// B-spline (cubic de Boor) evaluation, reformulated as per-span cubic
// polynomials + uniform-bin span lookup.
//
// Pipeline (all launched each call; graph-capturable, allocation-free):
//   1. sort_kernel:  rank-sort 1024 knots -> g_ts
//   2. coef_kernel:  per knot span i in [3,1020], run de Boor symbolically in
//                    double on polynomials in u = x - ts[i]; store float4 coeffs
//   3. bin_kernel:   8192 uniform bins over [ts[3], ts[1020]] -> starting span
//   4. eval_kernel:  persistent grid, tables in shared, float4 streaming I/O

#define KNOTS 1024
#define DEG   3
#define NBINS 8192
#define NVALID_LO DEG              // 3
#define NVALID_HI (KNOTS - DEG - 1) // 1020

__device__ float          g_ts[KNOTS];
__device__ float4         g_coef[KNOTS];
__device__ unsigned short g_bin[NBINS];

// ---------------------------------------------------------------------------
// 1. Rank sort: 1024 elements, 8 blocks x 128 threads, each block holds all
//    knots in shared; element i's rank = #{a<v} + #{a==v, idx<i} (stable).
// ---------------------------------------------------------------------------
__global__ void sort_kernel(const float* __restrict__ knots) {
    __shared__ float s[KNOTS];
    int t = threadIdx.x;
    for (int m = t; m < KNOTS; m += blockDim.x) s[m] = knots[m];
    __syncthreads();
    int i = blockIdx.x * blockDim.x + t;
    if (i < KNOTS) {
        float v = s[i];
        int rank = 0;
        #pragma unroll 8
        for (int m = 0; m < KNOTS; ++m) {
            float a = s[m];
            rank += (a < v) || (a == v && m < i);
        }
        g_ts[rank] = v;
    }
}

// ---------------------------------------------------------------------------
// 2. Per-span polynomial coefficients via symbolic de Boor (double precision).
//    Span i: valid for x with ts[i] < x <= ts[i+1]; local var u = x - ts[i].
//    Reference index algebra (p=3, k = i + p):
//      d_j^0  = c[i-3+j],                       j=0..3
//      tl     = ts[i+j-3],  tr = ts[i+j+1-r]
//      alpha  = (x - tl)/(tr - tl) = a0 + a1*u
//      d_j    = d_{j-1} + alpha*(d_j - d_{j-1})
// ---------------------------------------------------------------------------
__global__ void coef_kernel(const float* __restrict__ ctrl) {
    int i = blockIdx.x * blockDim.x + threadIdx.x + NVALID_LO;
    if (i > NVALID_HI) return;

    double T[7];                       // T[m] = ts[i-3+m], m = 0..6
    #pragma unroll
    for (int m = 0; m < 7; ++m) T[m] = (double)g_ts[i - 3 + m];
    double ti = T[3];

    double d[4][4];                    // d[j] = cubic poly coeffs in u
    #pragma unroll
    for (int j = 0; j < 4; ++j) {
        d[j][0] = (double)ctrl[i - 3 + j];
        d[j][1] = 0.0; d[j][2] = 0.0; d[j][3] = 0.0;
    }

    #pragma unroll
    for (int r = 1; r <= DEG; ++r) {
        #pragma unroll
        for (int j = DEG; j >= 1; --j) {
            if (j < r) continue;
            double tl = T[j];          // ts[i+j-3]
            double tr = T[j + 4 - r];  // ts[i+j+1-r]
            double a1 = 1.0 / (tr - tl);
            double a0 = (ti - tl) * a1;
            double e[4];
            #pragma unroll
            for (int m = 0; m < 4; ++m) e[m] = d[j][m] - d[j - 1][m];
            #pragma unroll
            for (int m = 0; m < 4; ++m) d[j][m] = d[j - 1][m] + a0 * e[m];
            #pragma unroll
            for (int m = 1; m < 4; ++m) d[j][m] += a1 * e[m - 1];
        }
    }
    g_coef[i] = make_float4((float)d[3][0], (float)d[3][1],
                            (float)d[3][2], (float)d[3][3]);
}

// ---------------------------------------------------------------------------
// 3. Bin table: bin b's left edge e = lo + b*w; entry = max{j : ts[j] < e},
//    clamped to valid span range. Eval scans forward from there.
// ---------------------------------------------------------------------------
__global__ void bin_kernel() {
    int b = blockIdx.x * blockDim.x + threadIdx.x;
    if (b >= NBINS) return;
    float lo = g_ts[NVALID_LO], hi = g_ts[NVALID_HI];
    float w  = (hi - lo) / (float)NBINS;
    float e  = lo + (float)b * w;
    int loI = 0, hiI = KNOTS;
    while (loI < hiI) {
        int mid = (loI + hiI) >> 1;
        if (g_ts[mid] < e) loI = mid + 1; else hiI = mid;
    }
    int start = loI - 1;
    if (start < NVALID_LO) start = NVALID_LO;
    if (start > NVALID_HI - 1) start = NVALID_HI - 1;
    g_bin[b] = (unsigned short)start;
}

// ---------------------------------------------------------------------------
// 4. Eval: persistent grid, 36 KB static shared tables, float4 stream.
// ---------------------------------------------------------------------------
__device__ __forceinline__ float eval_one(float x,
                                          const float* s_ts,
                                          const float4* s_coef,
                                          const unsigned short* s_bin,
                                          float lo, float invw) {
    int b = (int)((x - lo) * invw);
    b = min(max(b, 0), NBINS - 1);
    int i = (int)s_bin[b];
    // forward: i must be the largest index with ts[i] < x
    while (i < NVALID_HI - 1 && x > s_ts[i + 1]) ++i;
    float ti = s_ts[i];
    // backward safety (fp rounding at bin edges / exact-tie strictness)
    while (i > NVALID_LO && x <= ti) { --i; ti = s_ts[i]; }
    float u = x - ti;
    float4 cf = s_coef[i];
    return fmaf(fmaf(fmaf(cf.w, u, cf.z), u, cf.y), u, cf.x);
}

__global__ void __launch_bounds__(256)
eval_kernel(const float4* __restrict__ x4, float4* __restrict__ out4, int n4,
            const float* __restrict__ x_tail, float* __restrict__ out_tail,
            int n_tail) {
    __shared__ float          s_ts[KNOTS];
    __shared__ float4         s_coef[KNOTS];
    __shared__ unsigned short s_bin[NBINS];

    int t = threadIdx.x;
    for (int m = t; m < KNOTS; m += blockDim.x) {
        s_ts[m]   = g_ts[m];
        s_coef[m] = g_coef[m];
    }
    for (int m = t; m < NBINS; m += blockDim.x) s_bin[m] = g_bin[m];
    __syncthreads();

    float lo   = s_ts[NVALID_LO];
    float hi   = s_ts[NVALID_HI];
    float invw = (float)NBINS / (hi - lo);

    int stride = gridDim.x * blockDim.x;
    for (int idx = blockIdx.x * blockDim.x + t; idx < n4; idx += stride) {
        float4 xv = x4[idx];
        float4 r;
        r.x = eval_one(xv.x, s_ts, s_coef, s_bin, lo, invw);
        r.y = eval_one(xv.y, s_ts, s_coef, s_bin, lo, invw);
        r.z = eval_one(xv.z, s_ts, s_coef, s_bin, lo, invw);
        r.w = eval_one(xv.w, s_ts, s_coef, s_bin, lo, invw);
        out4[idx] = r;
    }
    // scalar tail (n % 4), handled by block 0
    if (blockIdx.x == 0 && t < n_tail) {
        out_tail[t] = eval_one(x_tail[t], s_ts, s_coef, s_bin, lo, invw);
    }
}

// ---------------------------------------------------------------------------
extern "C" void kernel_launch(void* const* d_in, const int* in_sizes, int n_in,
                              void* d_out, int out_size) {
    const float* x     = (const float*)d_in[0];   // [N_PTS]
    const float* knots = (const float*)d_in[1];   // [1024]
    const float* ctrl  = (const float*)d_in[2];   // [1021]
    float* out = (float*)d_out;

    int n  = in_sizes[0];
    int n4 = n >> 2;
    int n_tail = n & 3;

    sort_kernel<<<8, 128>>>(knots);
    coef_kernel<<<8, 128>>>(ctrl);                     // covers i = 3..1020
    bin_kernel<<<NBINS / 256, 256>>>();

    int blocks = 888;                                  // 148 SMs x 6 CTAs (36KB smem)
    eval_kernel<<<blocks, 256>>>((const float4*)x, (float4*)out, n4,
                                 x + (size_t)n4 * 4, out + (size_t)n4 * 4,
                                 n_tail);
}

// round 3
// speedup vs baseline: 1.2090x; 1.2090x over previous
#include <cuda_runtime.h>
#include <cuda_bf16.h>

// Cubic B-spline eval: per-span cubic polynomial records + uniform-bin lookup
// with clean/dirty flag.
//
//  1. sort_kernel:   rank-sort 1024 knots -> g_ts
//  2. setup2_kernel: blocks 0-3: per-span record {t, c0, c1, bf16(c3)|bf16(c2)}
//                    blocks 4-35: 8192-bin table, bit15 = "bin contains a knot"
//  3. eval_kernel:   persistent grid, 32KB shared tables, float4 streaming I/O
//     fast path (clean bin): 1 LDS.U16 + 1 LDS.128 per point.

#define KNOTS 1024
#define DEG   3
#define NBINS 8192
#define LOK   3        // first valid knot index (domain = (ts[3], ts[1020]))
#define HIK   1020     // last valid knot index; valid spans i in [3, 1019]

__device__ float          g_ts[KNOTS];
__device__ float4         g_rec[KNOTS];   // {ts[i], c0, c1, bf16 c3<<16 | bf16 c2}
__device__ unsigned short g_bin[NBINS];

// ---------------------------------------------------------------------------
// 1. Rank sort (stable): element i's rank = #{a<v} + #{a==v, idx<i}.
// ---------------------------------------------------------------------------
__global__ void sort_kernel(const float* __restrict__ knots) {
    __shared__ float s[KNOTS];
    int t = threadIdx.x;
    for (int m = t; m < KNOTS; m += blockDim.x) s[m] = knots[m];
    __syncthreads();
    int i = blockIdx.x * blockDim.x + t;
    if (i < KNOTS) {
        float v = s[i];
        int rank = 0;
        #pragma unroll 8
        for (int m = 0; m < KNOTS; ++m) {
            float a = s[m];
            rank += (a < v) || (a == v && m < i);
        }
        g_ts[rank] = v;
    }
}

// ---------------------------------------------------------------------------
// 2. Fused setup: span records (blocks 0-3) + bin table (blocks 4-35).
//    Record poly is in u = x - ts[i]; symbolic de Boor on poly coefficients.
// ---------------------------------------------------------------------------
__global__ void setup2_kernel(const float* __restrict__ ctrl) {
    if (blockIdx.x < 4) {
        int i = blockIdx.x * 256 + threadIdx.x;      // 0..1023
        float4 R;
        R.x = g_ts[i]; R.y = 0.f; R.z = 0.f; R.w = 0.f;
        if (i >= LOK && i <= HIK) {
            float T[7];
            #pragma unroll
            for (int m = 0; m < 7; ++m) T[m] = g_ts[i - 3 + m];
            float ti = T[3];
            float d[4][4];
            #pragma unroll
            for (int j = 0; j < 4; ++j) {
                d[j][0] = ctrl[i - 3 + j];
                d[j][1] = 0.f; d[j][2] = 0.f; d[j][3] = 0.f;
            }
            #pragma unroll
            for (int r = 1; r <= DEG; ++r) {
                #pragma unroll
                for (int j = DEG; j >= 1; --j) {
                    if (j < r) continue;
                    float tl = T[j];            // ts[i+j-3]
                    float tr = T[j + 4 - r];    // ts[i+j+1-r]
                    float den = tr - tl;
                    float a1 = (den != 0.f) ? (1.f / den) : 0.f;
                    float a0 = (ti - tl) * a1;
                    float e[4];
                    #pragma unroll
                    for (int m = 0; m < 4; ++m) e[m] = d[j][m] - d[j - 1][m];
                    #pragma unroll
                    for (int m = 0; m < 4; ++m) d[j][m] = d[j - 1][m] + a0 * e[m];
                    #pragma unroll
                    for (int m = 1; m < 4; ++m) d[j][m] += a1 * e[m - 1];
                }
            }
            R.y = d[3][0];
            R.z = d[3][1];
            unsigned c2b = (unsigned)__bfloat16_as_ushort(__float2bfloat16(d[3][2]));
            unsigned c3b = (unsigned)__bfloat16_as_ushort(__float2bfloat16(d[3][3]));
            R.w = __uint_as_float((c3b << 16) | c2b);
        }
        g_rec[i] = R;
    } else {
        int b = (blockIdx.x - 4) * 256 + threadIdx.x;  // 0..8191
        float lo = g_ts[LOK], hi = g_ts[HIK];
        float w  = (hi - lo) / (float)NBINS;
        float e0 = fmaf((float)b,       w, lo);
        float e1 = fmaf((float)(b + 1), w, lo);
        int s0, s1;
        #pragma unroll
        for (int pass = 0; pass < 2; ++pass) {
            float e = pass ? e1 : e0;
            int loI = 0, hiI = KNOTS;
            while (loI < hiI) {
                int mid = (loI + hiI) >> 1;
                if (g_ts[mid] < e) loI = mid + 1; else hiI = mid;
            }
            int s = loI - 1;
            if (s < LOK) s = LOK;
            if (s > HIK - 1) s = HIK - 1;
            if (pass) s1 = s; else s0 = s;
        }
        unsigned short entry = (unsigned short)s0;
        if (s0 != s1) entry |= 0x8000u;
        g_bin[b] = entry;
    }
}

// ---------------------------------------------------------------------------
// 3. Eval: fast path = LDS.U16 (bin) + LDS.128 (record) + 3 FFMA Horner.
// ---------------------------------------------------------------------------
__device__ __forceinline__ float eval_one(float x,
                                          const float4* s_rec,
                                          const unsigned short* s_bin,
                                          float nlo_invw, float invw) {
    int b = (int)fmaf(x, invw, nlo_invw);       // x in (lo+1e-3, hi-1e-3) => in range
    unsigned e = s_bin[b];
    int i = (int)(e & 0x7FFFu);
    if (e & 0x8000u) {                          // dirty bin: resolve span
        while (i < HIK - 1 && x > s_rec[i + 1].x) ++i;
    }
    float4 R = s_rec[i];
    while (i > LOK && x <= R.x) { --i; R = s_rec[i]; }   // fp-edge safety
    float u  = x - R.x;
    unsigned pw = __float_as_uint(R.w);
    float c2 = __uint_as_float(pw << 16);
    float c3 = __uint_as_float(pw & 0xFFFF0000u);
    return fmaf(fmaf(fmaf(c3, u, c2), u, R.z), u, R.y);
}

__global__ void __launch_bounds__(256)
eval_kernel(const float4* __restrict__ x4, float4* __restrict__ out4, int n4,
            const float* __restrict__ x_tail, float* __restrict__ out_tail,
            int n_tail) {
    __shared__ float4         s_rec[KNOTS];
    __shared__ unsigned short s_bin[NBINS];

    int t = threadIdx.x;
    for (int m = t; m < KNOTS; m += 256) s_rec[m] = g_rec[m];
    {
        const unsigned* src = (const unsigned*)g_bin;
        unsigned* dst = (unsigned*)s_bin;
        for (int m = t; m < NBINS / 2; m += 256) dst[m] = src[m];
    }
    __syncthreads();

    float lo   = s_rec[LOK].x;
    float hi   = s_rec[HIK].x;
    float invw = (float)NBINS / (hi - lo);
    float nlo_invw = -lo * invw;

    int stride = gridDim.x * blockDim.x;
    for (int idx = blockIdx.x * blockDim.x + t; idx < n4; idx += stride) {
        float4 xv = x4[idx];
        float4 r;
        r.x = eval_one(xv.x, s_rec, s_bin, nlo_invw, invw);
        r.y = eval_one(xv.y, s_rec, s_bin, nlo_invw, invw);
        r.z = eval_one(xv.z, s_rec, s_bin, nlo_invw, invw);
        r.w = eval_one(xv.w, s_rec, s_bin, nlo_invw, invw);
        out4[idx] = r;
    }
    if (blockIdx.x == 0 && t < n_tail) {
        out_tail[t] = eval_one(x_tail[t], s_rec, s_bin, nlo_invw, invw);
    }
}

// ---------------------------------------------------------------------------
extern "C" void kernel_launch(void* const* d_in, const int* in_sizes, int n_in,
                              void* d_out, int out_size) {
    const float* x     = (const float*)d_in[0];   // [N_PTS]
    const float* knots = (const float*)d_in[1];   // [1024]
    const float* ctrl  = (const float*)d_in[2];   // [1021]
    float* out = (float*)d_out;

    int n  = in_sizes[0];
    int n4 = n >> 2;
    int n_tail = n & 3;

    sort_kernel<<<8, 128>>>(knots);
    setup2_kernel<<<36, 256>>>(ctrl);   // 4 blocks records + 32 blocks bins

    int blocks = 888;                   // 148 SMs x 6 CTAs (32KB smem, 256 thr)
    eval_kernel<<<blocks, 256>>>((const float4*)x, (float4*)out, n4,
                                 x + (size_t)n4 * 4, out + (size_t)n4 * 4,
                                 n_tail);
}

// round 6
// speedup vs baseline: 1.3408x; 1.1091x over previous
#include <cuda_runtime.h>
#include <cuda_bf16.h>

// Cubic B-spline eval: per-span cubic polynomial records + uniform-bin lookup
// with clean/dirty flag.
//
//  1. sort_kernel:   warp-per-element rank sort of 1024 knots -> g_ts
//  2. setup2_kernel: blocks 0-3: per-span record {t, c0, c1, bf16(c3)|bf16(c2)}
//                    blocks 4-35: 8192-bin table, bit15 = "bin contains a knot"
//  3. eval_kernel:   persistent grid, 32KB shared tables, float4 streaming I/O
//     fast path (clean bin): 1 LDS.U16 + 1 LDS.128 per point.

#define KNOTS 1024
#define DEG   3
#define NBINS 8192
#define LOK   3        // first valid knot index (domain = (ts[3], ts[1020]))
#define HIK   1020     // last valid knot index; valid spans i in [3, 1019]

__device__ float          g_ts[KNOTS];
__device__ float4         g_rec[KNOTS];   // {ts[i], c0, c1, bf16 c3<<16 | bf16 c2}
__device__ unsigned short g_bin[NBINS];

// ---------------------------------------------------------------------------
// 1. Rank sort, warp-per-element: grid 128 x 256 threads. Block b owns
//    elements [8b, 8b+8); warp w computes rank of element 8b+w with 32-way
//    lane parallelism (stride-1 shared reads, conflict-free), then scatters.
//    rank = #{a<v} + #{a==v, idx<i}  (distinct ranks even for ties).
// ---------------------------------------------------------------------------
__global__ void __launch_bounds__(256)
sort_kernel(const float* __restrict__ knots) {
    __shared__ float s[KNOTS];
    int t = threadIdx.x;
    {
        float4* s4 = (float4*)s;
        const float4* k4 = (const float4*)knots;
        for (int m = t; m < KNOTS / 4; m += 256) s4[m] = k4[m];
    }
    __syncthreads();

    int wid  = t >> 5;
    int lane = t & 31;
    int i    = blockIdx.x * 8 + wid;       // element this warp ranks
    float v  = s[i];
    int cnt  = 0;
    #pragma unroll
    for (int k = 0; k < KNOTS / 32; ++k) {
        int m = (k << 5) + lane;
        float a = s[m];
        cnt += (a < v) || (a == v && m < i);
    }
    cnt = __reduce_add_sync(0xffffffffu, cnt);
    if (lane == 0) g_ts[cnt] = v;
}

// ---------------------------------------------------------------------------
// 2. Fused setup: span records (blocks 0-3) + bin table (blocks 4-35).
//    Record poly is in u = x - ts[i]; symbolic de Boor on poly coefficients.
// ---------------------------------------------------------------------------
__global__ void setup2_kernel(const float* __restrict__ ctrl) {
    if (blockIdx.x < 4) {
        int i = blockIdx.x * 256 + threadIdx.x;      // 0..1023
        float4 R;
        R.x = g_ts[i]; R.y = 0.f; R.z = 0.f; R.w = 0.f;
        if (i >= LOK && i <= HIK) {
            float T[7];
            #pragma unroll
            for (int m = 0; m < 7; ++m) T[m] = g_ts[i - 3 + m];
            float ti = T[3];
            float d[4][4];
            #pragma unroll
            for (int j = 0; j < 4; ++j) {
                d[j][0] = ctrl[i - 3 + j];
                d[j][1] = 0.f; d[j][2] = 0.f; d[j][3] = 0.f;
            }
            #pragma unroll
            for (int r = 1; r <= DEG; ++r) {
                #pragma unroll
                for (int j = DEG; j >= 1; --j) {
                    if (j < r) continue;
                    float tl = T[j];            // ts[i+j-3]
                    float tr = T[j + 4 - r];    // ts[i+j+1-r]
                    float den = tr - tl;
                    float a1 = (den != 0.f) ? (1.f / den) : 0.f;
                    float a0 = (ti - tl) * a1;
                    float e[4];
                    #pragma unroll
                    for (int m = 0; m < 4; ++m) e[m] = d[j][m] - d[j - 1][m];
                    #pragma unroll
                    for (int m = 0; m < 4; ++m) d[j][m] = d[j - 1][m] + a0 * e[m];
                    #pragma unroll
                    for (int m = 1; m < 4; ++m) d[j][m] += a1 * e[m - 1];
                }
            }
            R.y = d[3][0];
            R.z = d[3][1];
            unsigned c2b = (unsigned)__bfloat16_as_ushort(__float2bfloat16(d[3][2]));
            unsigned c3b = (unsigned)__bfloat16_as_ushort(__float2bfloat16(d[3][3]));
            R.w = __uint_as_float((c3b << 16) | c2b);
        }
        g_rec[i] = R;
    } else {
        int b = (blockIdx.x - 4) * 256 + threadIdx.x;  // 0..8191
        float lo = g_ts[LOK], hi = g_ts[HIK];
        float w  = (hi - lo) / (float)NBINS;
        float e0 = fmaf((float)b,       w, lo);
        float e1 = fmaf((float)(b + 1), w, lo);
        int s0, s1;
        #pragma unroll
        for (int pass = 0; pass < 2; ++pass) {
            float e = pass ? e1 : e0;
            int loI = 0, hiI = KNOTS;
            while (loI < hiI) {
                int mid = (loI + hiI) >> 1;
                if (g_ts[mid] < e) loI = mid + 1; else hiI = mid;
            }
            int s = loI - 1;
            if (s < LOK) s = LOK;
            if (s > HIK - 1) s = HIK - 1;
            if (pass) s1 = s; else s0 = s;
        }
        unsigned short entry = (unsigned short)s0;
        if (s0 != s1) entry |= 0x8000u;
        g_bin[b] = entry;
    }
}

// ---------------------------------------------------------------------------
// 3. Eval: fast path = LDS.U16 (bin) + LDS.128 (record) + 3 FFMA Horner.
// ---------------------------------------------------------------------------
__device__ __forceinline__ float eval_one(float x,
                                          const float4* s_rec,
                                          const unsigned short* s_bin,
                                          float nlo_invw, float invw) {
    int b = (int)fmaf(x, invw, nlo_invw);       // x in (lo+1e-3, hi-1e-3) => in range
    unsigned e = s_bin[b];
    int i = (int)(e & 0x7FFFu);
    if (e & 0x8000u) {                          // dirty bin: resolve span
        while (i < HIK - 1 && x > s_rec[i + 1].x) ++i;
    }
    float4 R = s_rec[i];
    while (i > LOK && x <= R.x) { --i; R = s_rec[i]; }   // fp-edge safety
    float u  = x - R.x;
    unsigned pw = __float_as_uint(R.w);
    float c2 = __uint_as_float(pw << 16);
    float c3 = __uint_as_float(pw & 0xFFFF0000u);
    return fmaf(fmaf(fmaf(c3, u, c2), u, R.z), u, R.y);
}

__device__ __forceinline__ float4 eval_four(float4 xv,
                                            const float4* s_rec,
                                            const unsigned short* s_bin,
                                            float nlo_invw, float invw) {
    float4 r;
    r.x = eval_one(xv.x, s_rec, s_bin, nlo_invw, invw);
    r.y = eval_one(xv.y, s_rec, s_bin, nlo_invw, invw);
    r.z = eval_one(xv.z, s_rec, s_bin, nlo_invw, invw);
    r.w = eval_one(xv.w, s_rec, s_bin, nlo_invw, invw);
    return r;
}

__global__ void __launch_bounds__(256)
eval_kernel(const float4* __restrict__ x4, float4* __restrict__ out4, int n4,
            const float* __restrict__ x_tail, float* __restrict__ out_tail,
            int n_tail) {
    __shared__ float4         s_rec[KNOTS];
    __shared__ unsigned short s_bin[NBINS];

    int t = threadIdx.x;
    for (int m = t; m < KNOTS; m += 256) s_rec[m] = g_rec[m];
    {
        const unsigned* src = (const unsigned*)g_bin;
        unsigned* dst = (unsigned*)s_bin;
        for (int m = t; m < NBINS / 2; m += 256) dst[m] = src[m];
    }
    __syncthreads();

    float lo   = s_rec[LOK].x;
    float hi   = s_rec[HIK].x;
    float invw = (float)NBINS / (hi - lo);
    float nlo_invw = -lo * invw;

    // 2-way ILP grid-stride: each block covers 512 float4 per sweep.
    int stride = gridDim.x * 512;
    for (int idx = blockIdx.x * 512 + t; idx < n4; idx += stride) {
        int idx2 = idx + 256;
        float4 xa = x4[idx];
        bool has2 = (idx2 < n4);
        float4 xb = has2 ? x4[idx2] : xa;
        float4 ra = eval_four(xa, s_rec, s_bin, nlo_invw, invw);
        float4 rb = eval_four(xb, s_rec, s_bin, nlo_invw, invw);
        out4[idx] = ra;
        if (has2) out4[idx2] = rb;
    }
    if (blockIdx.x == 0 && t < n_tail) {
        out_tail[t] = eval_one(x_tail[t], s_rec, s_bin, nlo_invw, invw);
    }
}

// ---------------------------------------------------------------------------
extern "C" void kernel_launch(void* const* d_in, const int* in_sizes, int n_in,
                              void* d_out, int out_size) {
    const float* x     = (const float*)d_in[0];   // [N_PTS]
    const float* knots = (const float*)d_in[1];   // [1024]
    const float* ctrl  = (const float*)d_in[2];   // [1021]
    float* out = (float*)d_out;

    int n  = in_sizes[0];
    int n4 = n >> 2;
    int n_tail = n & 3;

    sort_kernel<<<KNOTS / 8, 256>>>(knots);   // 128 blocks, warp-per-element
    setup2_kernel<<<36, 256>>>(ctrl);         // 4 blocks records + 32 blocks bins

    int blocks = 888;                         // 148 SMs x 6 CTAs (32KB smem)
    eval_kernel<<<blocks, 256>>>((const float4*)x, (float4*)out, n4,
                                 x + (size_t)n4 * 4, out + (size_t)n4 * 4,
                                 n_tail);
}